// round 3
// baseline (speedup 1.0000x reference)
#include <cuda_runtime.h>
#include <stdint.h>
#include <math.h>

#define NMAX 100000
#define EMAX 3200000
#define GMAX 128
#define H 32

// Scratch (device globals; zero-initialized at module load, self-cleaned per call)
__device__ int   g_deg[NMAX];          // atomic counts; zeroed by k_scan after read
__device__ float g_dinv[NMAX];
__device__ float g_xs[NMAX];           // dinv[i] * x[i]
__device__ int   g_rowstart[NMAX + 1];
__device__ int   g_cursor[NMAX];
__device__ int   g_csr[EMAX];
__device__ float g_hsA[NMAX * H];      // hs for layer-2 gather
__device__ float g_hsB[NMAX * H];      // hs for layer-3 gather
__device__ float g_gsum[GMAX * H];     // pooling accum; zeroed by k_graph after read
__device__ float g_gcnt[GMAX];

// ---------------- CSR build ----------------

__global__ void k_count_v4(const int* __restrict__ dst, int e4) {
    int i = blockIdx.x * blockDim.x + threadIdx.x;
    if (i < e4) {
        int4 d = ((const int4*)dst)[i];
        atomicAdd(&g_deg[d.x], 1);
        atomicAdd(&g_deg[d.y], 1);
        atomicAdd(&g_deg[d.z], 1);
        atomicAdd(&g_deg[d.w], 1);
    }
}
__global__ void k_count_s(const int* __restrict__ dst, int e) {
    int i = blockIdx.x * blockDim.x + threadIdx.x;
    if (i < e) atomicAdd(&g_deg[dst[i]], 1);
}

// Single-block scan of neighbor counts -> rowstart/cursor; dinv, xs; zero deg.
__global__ void k_scan(const float* __restrict__ x, int n) {
    const int K = 4;
    __shared__ int warp_sums[32];
    __shared__ int sh_carry;
    int tid = threadIdx.x, lane = tid & 31, wid = tid >> 5;
    if (tid == 0) sh_carry = 0;
    __syncthreads();
    for (int base = 0; base < n; base += 1024 * K) {
        int v[K];
        int local = 0;
#pragma unroll
        for (int k = 0; k < K; k++) {
            int i = base + tid * K + k;
            v[k] = (i < n) ? g_deg[i] : 0;
            local += v[k];
        }
        int incl = local;
#pragma unroll
        for (int o = 1; o < 32; o <<= 1) {
            int t = __shfl_up_sync(0xffffffffu, incl, o);
            if (lane >= o) incl += t;
        }
        if (lane == 31) warp_sums[wid] = incl;
        __syncthreads();
        int carry = sh_carry;
        __syncthreads();
        if (tid == 0) {
            int run = 0;
#pragma unroll
            for (int w = 0; w < 32; w++) { int t = warp_sums[w]; warp_sums[w] = run; run += t; }
            sh_carry = carry + run;
        }
        __syncthreads();
        int excl = carry + warp_sums[wid] + (incl - local);
#pragma unroll
        for (int k = 0; k < K; k++) {
            int i = base + tid * K + k;
            if (i < n) {
                g_rowstart[i] = excl;
                g_cursor[i]   = excl;
                float dinv = rsqrtf((float)(v[k] + 1));   // +1 self loop
                g_dinv[i] = dinv;
                g_xs[i]   = dinv * x[i];
                g_deg[i]  = 0;                            // self-clean for next call
            }
            excl += v[k];
        }
        __syncthreads();
    }
    if (tid == 0) g_rowstart[n] = sh_carry;
}

__global__ void k_scatter_v4(const int* __restrict__ src, const int* __restrict__ dst, int e4) {
    int i = blockIdx.x * blockDim.x + threadIdx.x;
    if (i < e4) {
        int4 d = ((const int4*)dst)[i];
        int4 s = ((const int4*)src)[i];
        g_csr[atomicAdd(&g_cursor[d.x], 1)] = s.x;
        g_csr[atomicAdd(&g_cursor[d.y], 1)] = s.y;
        g_csr[atomicAdd(&g_cursor[d.z], 1)] = s.z;
        g_csr[atomicAdd(&g_cursor[d.w], 1)] = s.w;
    }
}
__global__ void k_scatter_s(const int* __restrict__ src, const int* __restrict__ dst, int e) {
    int i = blockIdx.x * blockDim.x + threadIdx.x;
    if (i < e) {
        int d = dst[i];
        g_csr[atomicAdd(&g_cursor[d], 1)] = src[i];
    }
}

// ---------------- Layer 1 (scalar gather, rank-1) + transform by W2 ----------------

__global__ void k_l1(const float* __restrict__ W1, const float* __restrict__ b1,
                     const float* __restrict__ W2, int n) {
    __shared__ float Ws[H * H];
    int tid = threadIdx.x;
    for (int t = tid; t < H * H; t += 256) Ws[t] = W2[t];
    __syncthreads();
    int i = (blockIdx.x * blockDim.x + tid) >> 5;
    int lane = tid & 31;
    if (i >= n) return;
    float dinv_i = g_dinv[i];
    int st = g_rowstart[i], en = g_rowstart[i + 1];
    float s = 0.f;
    for (int e = st + lane; e < en; e += 32)
        s += g_xs[__ldg(&g_csr[e])];
#pragma unroll
    for (int o = 16; o > 0; o >>= 1) s += __shfl_xor_sync(0xffffffffu, s, o);
    float S = s + g_xs[i];   // + self-loop term
    float x1 = fmaxf(dinv_i * S * __ldg(&W1[lane]) + __ldg(&b1[lane]), 0.f);
    // hs2 = (x1 @ W2) * dinv
    float acc = 0.f;
#pragma unroll
    for (int k = 0; k < H; k++)
        acc += __shfl_sync(0xffffffffu, x1, k) * Ws[k * H + lane];
    g_hsA[i * H + lane] = acc * dinv_i;
}

// ---------------- Layer 2 gather + transform by W3 ----------------

__global__ void k_g2(const float* __restrict__ b2, const float* __restrict__ W3, int n) {
    __shared__ float Ws[H * H];
    int tid = threadIdx.x;
    for (int t = tid; t < H * H; t += 256) Ws[t] = W3[t];
    __syncthreads();
    int i = (blockIdx.x * blockDim.x + tid) >> 5;
    int lane = tid & 31;
    if (i >= n) return;
    float dinv_i = g_dinv[i];
    int st = g_rowstart[i], en = g_rowstart[i + 1];
    float s0 = g_hsA[i * H + lane];   // self term (pre-scaled)
    float s1 = 0.f;
    int e = st;
    while (en - e >= 32) {
        int idx = __ldg(&g_csr[e + lane]);
#pragma unroll
        for (int t = 0; t < 32; t += 2) {
            int j0 = __shfl_sync(0xffffffffu, idx, t);
            int j1 = __shfl_sync(0xffffffffu, idx, t + 1);
            s0 += g_hsA[j0 * H + lane];
            s1 += g_hsA[j1 * H + lane];
        }
        e += 32;
    }
    int m = en - e;
    if (m > 0) {
        int idx = (lane < m) ? __ldg(&g_csr[e + lane]) : 0;
        for (int t = 0; t < m; t++) {
            int j0 = __shfl_sync(0xffffffffu, idx, t);
            s0 += g_hsA[j0 * H + lane];
        }
    }
    float x2 = fmaxf((s0 + s1) * dinv_i + __ldg(&b2[lane]), 0.f);
    float acc = 0.f;
#pragma unroll
    for (int k = 0; k < H; k++)
        acc += __shfl_sync(0xffffffffu, x2, k) * Ws[k * H + lane];
    g_hsB[i * H + lane] = acc * dinv_i;
}

// ---------------- Layer 3 gather + theta head + pooling ----------------

__global__ void k_g3(const float* __restrict__ b3, const int* __restrict__ batch,
                     const float* __restrict__ Wt1, const float* __restrict__ bt1,
                     const float* __restrict__ Wt2, const float* __restrict__ bt2,
                     float* __restrict__ out, int n) {
    __shared__ float Ws[H * H];   // Wt1
    int tid = threadIdx.x;
    for (int t = tid; t < H * H; t += 256) Ws[t] = Wt1[t];
    __syncthreads();
    int i = (blockIdx.x * blockDim.x + tid) >> 5;
    int lane = tid & 31;
    if (i >= n) return;
    float dinv_i = g_dinv[i];
    int st = g_rowstart[i], en = g_rowstart[i + 1];
    float s0 = g_hsB[i * H + lane];
    float s1 = 0.f;
    int e = st;
    while (en - e >= 32) {
        int idx = __ldg(&g_csr[e + lane]);
#pragma unroll
        for (int t = 0; t < 32; t += 2) {
            int j0 = __shfl_sync(0xffffffffu, idx, t);
            int j1 = __shfl_sync(0xffffffffu, idx, t + 1);
            s0 += g_hsB[j0 * H + lane];
            s1 += g_hsB[j1 * H + lane];
        }
        e += 32;
    }
    int m = en - e;
    if (m > 0) {
        int idx = (lane < m) ? __ldg(&g_csr[e + lane]) : 0;
        for (int t = 0; t < m; t++) {
            int j0 = __shfl_sync(0xffffffffu, idx, t);
            s0 += g_hsB[j0 * H + lane];
        }
    }
    float h = fmaxf((s0 + s1) * dinv_i + __ldg(&b3[lane]), 0.f);
    // theta head
    float acc = __ldg(&bt1[lane]);
#pragma unroll
    for (int k = 0; k < H; k++)
        acc += __shfl_sync(0xffffffffu, h, k) * Ws[k * H + lane];
    float p = fmaxf(acc, 0.f) * __ldg(&Wt2[lane]);
#pragma unroll
    for (int o = 16; o > 0; o >>= 1) p += __shfl_xor_sync(0xffffffffu, p, o);
    // pooling
    int g = batch[i];
    atomicAdd(&g_gsum[g * H + lane], h);
    if (lane == 0) {
        atomicAdd(&g_gcnt[g], 1.f);
        float z = p + __ldg(&bt2[0]);
        out[i] = 3.14159265358979323846f / (1.f + expf(-z));
    }
}

// ---------------- Per-graph MLP head (+ self-clean) ----------------

__global__ void k_graph(const float* __restrict__ Wg1, const float* __restrict__ bg1,
                        const float* __restrict__ Wg2, const float* __restrict__ bg2,
                        float* __restrict__ out, int n, int g) {
    int wid = (blockIdx.x * blockDim.x + threadIdx.x) >> 5;
    int lane = threadIdx.x & 31;
    if (wid >= g) return;
    float cnt = g_gcnt[wid];
    float ge = g_gsum[wid * H + lane] / fmaxf(cnt, 1.f);
    // self-clean for next call
    g_gsum[wid * H + lane] = 0.f;
    if (lane == 0) g_gcnt[wid] = 0.f;
    float acc = __ldg(&bg1[lane]);
#pragma unroll
    for (int k = 0; k < H; k++)
        acc += __shfl_sync(0xffffffffu, ge, k) * __ldg(&Wg1[k * H + lane]);
    float t = fmaxf(acc, 0.f);
    float p0 = t * __ldg(&Wg2[lane * 2 + 0]);
    float p1 = t * __ldg(&Wg2[lane * 2 + 1]);
#pragma unroll
    for (int o = 16; o > 0; o >>= 1) {
        p0 += __shfl_xor_sync(0xffffffffu, p0, o);
        p1 += __shfl_xor_sync(0xffffffffu, p1, o);
    }
    if (lane == 0) {
        const float TWO_PI = 6.28318530717958647692f;
        out[n + wid * 2 + 0] = TWO_PI / (1.f + expf(-(p0 + __ldg(&bg2[0]))));
        out[n + wid * 2 + 1] = TWO_PI / (1.f + expf(-(p1 + __ldg(&bg2[1]))));
    }
}

extern "C" void kernel_launch(void* const* d_in, const int* in_sizes, int n_in,
                              void* d_out, int out_size) {
    const float* x   = (const float*)d_in[0];
    const int*   ei  = (const int*)d_in[1];
    const int*   bat = (const int*)d_in[2];
    const float* W1  = (const float*)d_in[3];
    const float* b1  = (const float*)d_in[4];
    const float* W2  = (const float*)d_in[5];
    const float* b2  = (const float*)d_in[6];
    const float* W3  = (const float*)d_in[7];
    const float* b3  = (const float*)d_in[8];
    const float* Wt1 = (const float*)d_in[9];
    const float* bt1 = (const float*)d_in[10];
    const float* Wt2 = (const float*)d_in[11];
    const float* bt2 = (const float*)d_in[12];
    const float* Wg1 = (const float*)d_in[13];
    const float* bg1 = (const float*)d_in[14];
    const float* Wg2 = (const float*)d_in[15];
    const float* bg2 = (const float*)d_in[16];
    float* out = (float*)d_out;

    int N = in_sizes[0];
    int E = in_sizes[1] / 2;
    int G = (out_size - N) / 2;

    const int* src = ei;
    const int* dst = ei + E;

    const int TB = 256;
    int nb_w = (N * 32 + TB - 1) / TB;
    int nb_g = (G * 32 + TB - 1) / TB;

    bool vec4 = ((E & 3) == 0) &&
                ((((unsigned long long)src) & 15ull) == 0) &&
                ((((unsigned long long)dst) & 15ull) == 0);

    if (vec4) {
        int e4 = E / 4;
        int nb = (e4 + TB - 1) / TB;
        k_count_v4<<<nb, TB>>>(dst, e4);
        k_scan<<<1, 1024>>>(x, N);
        k_scatter_v4<<<nb, TB>>>(src, dst, e4);
    } else {
        int nb = (E + TB - 1) / TB;
        k_count_s<<<nb, TB>>>(dst, E);
        k_scan<<<1, 1024>>>(x, N);
        k_scatter_s<<<nb, TB>>>(src, dst, E);
    }

    k_l1<<<nb_w, TB>>>(W1, b1, W2, N);
    k_g2<<<nb_w, TB>>>(b2, W3, N);
    k_g3<<<nb_w, TB>>>(b3, bat, Wt1, bt1, Wt2, bt2, out, N);
    k_graph<<<nb_g, TB>>>(Wg1, bg1, Wg2, bg2, out, N, G);
}